// round 1
// baseline (speedup 1.0000x reference)
#include <cuda_runtime.h>
#include <cuda_bf16.h>
#include <cstdint>

// ---------------------------------------------------------------------------
// ConvKanModel: 2x [ base_conv(silu(x)) + spline_conv(bspline_bases(x)) ->
//                    instance_norm -> prelu ], then sigmoid.
// x: (4,16,512,512) f32.  K = 11 bases (GRID_SIZE=8, ORDER=3), grid knots
// g[i] = -1.75 + 0.25*i.  Cubic B-spline on uniform grid -> closed form:
// cell = floor((x+1.75)*4), t = frac; 4 nonzero bases (cell-3..cell) with
// standard cubic weights. Out-of-range x -> all bases zero (matches ref).
// ---------------------------------------------------------------------------

#define NB      4
#define CCH     16
#define KB      11          // number of stored bases
#define JF      12          // features per channel: silu + 11 bases
#define HW      512
#define PLANE   (HW*HW)     // 262144
#define TOTAL   (NB*CCH*PLANE)

#define TILE    32
#define HALO    (TILE+2)        // 34
#define HALO2   (HALO*HALO)     // 1156
#define NW      (JF*3*3*CCH)    // 1728 combined weights per input channel
#define SMEM_BYTES ((JF*HALO2 + NW) * 4)   // 62400 B

// Scratch (static device globals; no runtime allocation)
__device__ float g_z1[TOTAL];
__device__ float g_z2[TOTAL];
__device__ float g_m1[NB*CCH];
__device__ float g_r1[NB*CCH];
__device__ float g_m2[NB*CCH];
__device__ float g_r2[NB*CCH];

// ---------------------------------------------------------------------------
// Fused KAN conv: builds per-channel activation tile (silu + 4-sparse bases)
// in shared memory, then direct 3x3 conv over 12 features x 16 channels into
// 16 output channels. Optionally applies instance-norm + prelu to the input
// (for layer 2, reading raw pre-norm z1).
// Block: 256 threads. Tile: 32x32 pixels, all 16 out channels.
// Thread: 8 pixels (one column, 8 consecutive rows) x 8 out channels.
// ---------------------------------------------------------------------------
template<bool NORM>
__global__ __launch_bounds__(256, 2)
void conv_kan_kernel(const float* __restrict__ in,
                     const float* __restrict__ base_w,    // [16][16][3][3]
                     const float* __restrict__ spline_w,  // [16][176][3][3]
                     const float* __restrict__ mean,
                     const float* __restrict__ rstd,
                     const float* __restrict__ alpha_p,
                     float* __restrict__ out)
{
    extern __shared__ float smem[];
    float* s_act = smem;                 // [JF][HALO2]
    float* s_w   = smem + JF*HALO2;      // [JF][3][3][16]

    const int tid    = threadIdx.x;
    const int col    = tid & 31;         // 0..31  (x within tile)
    const int rowgrp = (tid >> 5) & 3;   // 0..3   (8-row group)
    const int ohalf  = tid >> 7;         // 0..1   (out-channel half)
    const int bx     = blockIdx.x * TILE;
    const int by     = blockIdx.y * TILE;
    const int b      = blockIdx.z;

    const float alpha = NORM ? alpha_p[0] : 0.0f;

    float acc[8][8];
#pragma unroll
    for (int r = 0; r < 8; ++r)
#pragma unroll
        for (int o = 0; o < 8; ++o) acc[r][o] = 0.0f;

    for (int c = 0; c < CCH; ++c) {
        __syncthreads();   // protect previous iteration's reads

        // ---- build activation tile for input channel c ----
        const float* inp = in + ((size_t)(b*CCH + c)) * PLANE;
        float mu = 0.0f, rs = 0.0f;
        if (NORM) { mu = mean[b*CCH + c]; rs = rstd[b*CCH + c]; }

        for (int idx = tid; idx < HALO2; idx += 256) {
            const int iy = idx / HALO;
            const int ix = idx - iy * HALO;
            const int gy = by + iy - 1;
            const int gx = bx + ix - 1;

            float a0 = 0.0f, w0 = 0.0f, w1 = 0.0f, w2 = 0.0f, w3 = 0.0f;
            int cell = -100;
            if (gy >= 0 && gy < HW && gx >= 0 && gx < HW) {
                float x = inp[gy*HW + gx];
                if (NORM) {
                    x = (x - mu) * rs;
                    x = (x < 0.0f) ? alpha * x : x;   // prelu
                }
                a0 = x / (1.0f + __expf(-x));          // silu
                const float u  = (x + 1.75f) * 4.0f;
                const float cf = floorf(u);
                const int ci = (int)cf;
                if (ci >= 0 && ci < 14) {
                    cell = ci;
                    const float t  = u - cf;
                    const float mt = 1.0f - t;
                    const float t2 = t*t, t3 = t2*t;
                    w0 = mt*mt*mt * (1.0f/6.0f);
                    w1 = (3.0f*t3 - 6.0f*t2 + 4.0f) * (1.0f/6.0f);
                    w2 = (-3.0f*t3 + 3.0f*t2 + 3.0f*t + 1.0f) * (1.0f/6.0f);
                    w3 = t3 * (1.0f/6.0f);
                }
            }
            s_act[idx] = a0;                     // feature 0 = silu
#pragma unroll
            for (int j = 1; j < JF; ++j) s_act[j*HALO2 + idx] = 0.0f;
            if (cell >= 0) {
                // basis index = cell-3..cell; stored bases are 0..10 -> slot j=idx+1
                if (cell >= 3)               s_act[(cell-2)*HALO2 + idx] = w0;
                if (cell >= 2 && cell <= 12) s_act[(cell-1)*HALO2 + idx] = w1;
                if (cell >= 1 && cell <= 11) s_act[(cell  )*HALO2 + idx] = w2;
                if (cell <= 10)              s_act[(cell+1)*HALO2 + idx] = w3;
            }
        }

        // ---- load combined weights for channel c: [j][ky][kx][o] ----
        for (int idx = tid; idx < NW; idx += 256) {
            const int o    = idx & 15;
            const int rest = idx >> 4;        // 0..107
            const int kx   = rest % 3;
            const int ky   = (rest / 3) % 3;
            const int j    = rest / 9;        // 0..11
            float w;
            if (j == 0) w = base_w[((o*CCH + c)*3 + ky)*3 + kx];
            else        w = spline_w[((o*(CCH*KB) + (c*KB + j - 1))*3 + ky)*3 + kx];
            s_w[((j*3 + ky)*3 + kx)*CCH + o] = w;
        }
        __syncthreads();

        // ---- accumulate: 12 features x 9 taps ----
        const int rbase = rowgrp * 8;
        for (int j = 0; j < JF; ++j) {
            const float* actj = s_act + j*HALO2;
            const float* wj   = s_w + j*9*CCH + ohalf*8;
#pragma unroll
            for (int ky = 0; ky < 3; ++ky) {
#pragma unroll
                for (int kx = 0; kx < 3; ++kx) {
                    float wv[8];
#pragma unroll
                    for (int oo = 0; oo < 8; ++oo)
                        wv[oo] = wj[(ky*3 + kx)*CCH + oo];
                    float av[8];
#pragma unroll
                    for (int r = 0; r < 8; ++r)
                        av[r] = actj[(rbase + r + ky)*HALO + col + kx];
#pragma unroll
                    for (int r = 0; r < 8; ++r)
#pragma unroll
                        for (int oo = 0; oo < 8; ++oo)
                            acc[r][oo] = fmaf(av[r], wv[oo], acc[r][oo]);
                }
            }
        }
    }

    // ---- epilogue: write 8 pixels x 8 out channels ----
#pragma unroll
    for (int oo = 0; oo < 8; ++oo) {
        const int o = ohalf*8 + oo;
        float* op = out + ((size_t)(b*CCH + o)) * PLANE;
#pragma unroll
        for (int r = 0; r < 8; ++r) {
            const int gy = by + rowgrp*8 + r;
            op[gy*HW + bx + col] = acc[r][oo];
        }
    }
}

// ---------------------------------------------------------------------------
// Per-(b,c) mean / rstd over one 512x512 plane. 64 blocks, deterministic.
// ---------------------------------------------------------------------------
__global__ void stats_kernel(const float* __restrict__ z,
                             float* __restrict__ mean,
                             float* __restrict__ rstd)
{
    __shared__ float sh_s[1024];
    __shared__ float sh_q[1024];
    const int bc = blockIdx.x;
    const float* p = z + (size_t)bc * PLANE;
    float s = 0.0f, q = 0.0f;
    for (int i = threadIdx.x; i < PLANE; i += 1024) {
        const float v = p[i];
        s += v; q += v*v;
    }
    sh_s[threadIdx.x] = s;
    sh_q[threadIdx.x] = q;
    __syncthreads();
    for (int off = 512; off > 0; off >>= 1) {
        if (threadIdx.x < off) {
            sh_s[threadIdx.x] += sh_s[threadIdx.x + off];
            sh_q[threadIdx.x] += sh_q[threadIdx.x + off];
        }
        __syncthreads();
    }
    if (threadIdx.x == 0) {
        const float m   = sh_s[0] * (1.0f / PLANE);
        const float var = sh_q[0] * (1.0f / PLANE) - m*m;
        mean[bc] = m;
        rstd[bc] = rsqrtf(var + 1e-5f);
    }
}

// ---------------------------------------------------------------------------
// out = sigmoid(prelu((z - mean)*rstd, alpha))
// ---------------------------------------------------------------------------
__global__ void finalize_kernel(const float* __restrict__ z,
                                const float* __restrict__ mean,
                                const float* __restrict__ rstd,
                                const float* __restrict__ alpha_p,
                                float* __restrict__ out)
{
    const size_t i = (size_t)blockIdx.x * blockDim.x + threadIdx.x;
    if (i >= TOTAL) return;
    const int bc = (int)(i >> 18);   // / PLANE
    const float alpha = alpha_p[0];
    float v = (z[i] - mean[bc]) * rstd[bc];
    v = (v < 0.0f) ? alpha * v : v;
    out[i] = 1.0f / (1.0f + __expf(-v));
}

// ---------------------------------------------------------------------------
extern "C" void kernel_launch(void* const* d_in, const int* in_sizes, int n_in,
                              void* d_out, int out_size)
{
    const float* x   = (const float*)d_in[0];
    const float* bw1 = (const float*)d_in[1];
    const float* sw1 = (const float*)d_in[2];
    const float* a1  = (const float*)d_in[3];
    const float* bw2 = (const float*)d_in[4];
    const float* sw2 = (const float*)d_in[5];
    const float* a2  = (const float*)d_in[6];
    float* out = (float*)d_out;

    float *z1, *z2, *m1, *r1, *m2, *r2;
    cudaGetSymbolAddress((void**)&z1, g_z1);
    cudaGetSymbolAddress((void**)&z2, g_z2);
    cudaGetSymbolAddress((void**)&m1, g_m1);
    cudaGetSymbolAddress((void**)&r1, g_r1);
    cudaGetSymbolAddress((void**)&m2, g_m2);
    cudaGetSymbolAddress((void**)&r2, g_r2);

    cudaFuncSetAttribute(conv_kan_kernel<false>,
                         cudaFuncAttributeMaxDynamicSharedMemorySize, SMEM_BYTES);
    cudaFuncSetAttribute(conv_kan_kernel<true>,
                         cudaFuncAttributeMaxDynamicSharedMemorySize, SMEM_BYTES);

    const dim3 grid(HW/TILE, HW/TILE, NB);   // 16 x 16 x 4

    // Layer 1
    conv_kan_kernel<false><<<grid, 256, SMEM_BYTES>>>(
        x, bw1, sw1, nullptr, nullptr, nullptr, z1);
    stats_kernel<<<NB*CCH, 1024>>>(z1, m1, r1);

    // Layer 2 (norm+prelu of layer-1 output fused into its input load)
    conv_kan_kernel<true><<<grid, 256, SMEM_BYTES>>>(
        z1, bw2, sw2, m1, r1, a1, z2);
    stats_kernel<<<NB*CCH, 1024>>>(z2, m2, r2);

    // Final norm + prelu + sigmoid
    finalize_kernel<<<(TOTAL + 255)/256, 256>>>(z2, m2, r2, a2, out);
}

// round 2
// speedup vs baseline: 1.1121x; 1.1121x over previous
#include <cuda_runtime.h>
#include <cuda_bf16.h>
#include <cstdint>

// ---------------------------------------------------------------------------
// ConvKanModel: 2x [ base_conv(silu(x)) + spline_conv(bspline_bases(x)) ->
//                    instance_norm -> prelu ], then sigmoid.
// x: (4,16,512,512) f32.  Cubic B-spline on uniform grid -> closed form:
// cell = floor((x+1.75)*4); 4 nonzero bases with standard cubic weights.
// This round: inner conv loop uses packed fma.rn.f32x2 (2 lane-FMA/inst,
// 128 lane-FMA/cyc/SM vs 64 scalar) pairing adjacent output channels.
// ---------------------------------------------------------------------------

#define NB      4
#define CCH     16
#define KB      11          // number of stored bases
#define JF      12          // features per channel: silu + 11 bases
#define HW      512
#define PLANE   (HW*HW)     // 262144
#define TOTAL   (NB*CCH*PLANE)

#define TILE    32
#define HALO    (TILE+2)        // 34
#define HALO2   (HALO*HALO)     // 1156
#define NW      (JF*3*3*CCH)    // 1728 combined weights per input channel
#define SMEM_BYTES ((JF*HALO2 + NW) * 4)   // 62400 B

// Scratch (static device globals; no runtime allocation)
__device__ float g_z1[TOTAL];
__device__ float g_z2[TOTAL];
__device__ float g_m1[NB*CCH];
__device__ float g_r1[NB*CCH];
__device__ float g_m2[NB*CCH];
__device__ float g_r2[NB*CCH];

// ---- packed fp32x2 helpers (sm_103a packed pipe; ptxas won't auto-emit) ----
__device__ __forceinline__ unsigned long long pack2(float x) {
    unsigned long long r;
    asm("mov.b64 %0, {%1, %1};" : "=l"(r) : "f"(x));
    return r;
}
__device__ __forceinline__ void fma2(unsigned long long& d,
                                     unsigned long long a,
                                     unsigned long long b) {
    asm("fma.rn.f32x2 %0, %1, %2, %0;" : "+l"(d) : "l"(a), "l"(b));
}

// ---------------------------------------------------------------------------
// Fused KAN conv. Block: 256 threads, 32x32 pixel tile, all 16 out channels.
// Thread: 8 pixels (one column, 8 consecutive rows) x 8 out channels
// (4 packed f32x2 accumulator pairs).
// ---------------------------------------------------------------------------
template<bool NORM>
__global__ __launch_bounds__(256, 2)
void conv_kan_kernel(const float* __restrict__ in,
                     const float* __restrict__ base_w,    // [16][16][3][3]
                     const float* __restrict__ spline_w,  // [16][176][3][3]
                     const float* __restrict__ mean,
                     const float* __restrict__ rstd,
                     const float* __restrict__ alpha_p,
                     float* __restrict__ out)
{
    extern __shared__ float smem[];
    float* s_act = smem;                 // [JF][HALO2]
    float* s_w   = smem + JF*HALO2;      // [JF][3][3][16]  (16 = outch, contiguous)

    const int tid    = threadIdx.x;
    const int col    = tid & 31;         // 0..31  (x within tile)
    const int rowgrp = (tid >> 5) & 3;   // 0..3   (8-row group)
    const int ohalf  = tid >> 7;         // 0..1   (out-channel half)
    const int bx     = blockIdx.x * TILE;
    const int by     = blockIdx.y * TILE;
    const int b      = blockIdx.z;

    const float alpha = NORM ? alpha_p[0] : 0.0f;

    // 8 rows x 4 outch-pairs of packed f32x2 accumulators
    unsigned long long acc[8][4];
#pragma unroll
    for (int r = 0; r < 8; ++r)
#pragma unroll
        for (int p = 0; p < 4; ++p) acc[r][p] = 0ull;

    for (int c = 0; c < CCH; ++c) {
        __syncthreads();   // protect previous iteration's reads

        // ---- build activation tile for input channel c ----
        const float* inp = in + ((size_t)(b*CCH + c)) * PLANE;
        float mu = 0.0f, rs = 0.0f;
        if (NORM) { mu = mean[b*CCH + c]; rs = rstd[b*CCH + c]; }

        for (int idx = tid; idx < HALO2; idx += 256) {
            const int iy = idx / HALO;
            const int ix = idx - iy * HALO;
            const int gy = by + iy - 1;
            const int gx = bx + ix - 1;

            float a0 = 0.0f, w0 = 0.0f, w1 = 0.0f, w2 = 0.0f, w3 = 0.0f;
            int cell = -100;
            if (gy >= 0 && gy < HW && gx >= 0 && gx < HW) {
                float x = inp[gy*HW + gx];
                if (NORM) {
                    x = (x - mu) * rs;
                    x = (x < 0.0f) ? alpha * x : x;   // prelu
                }
                a0 = x / (1.0f + __expf(-x));          // silu
                const float u  = (x + 1.75f) * 4.0f;
                const float cf = floorf(u);
                const int ci = (int)cf;
                if (ci >= 0 && ci < 14) {
                    cell = ci;
                    const float t  = u - cf;
                    const float mt = 1.0f - t;
                    const float t2 = t*t, t3 = t2*t;
                    w0 = mt*mt*mt * (1.0f/6.0f);
                    w1 = (3.0f*t3 - 6.0f*t2 + 4.0f) * (1.0f/6.0f);
                    w2 = (-3.0f*t3 + 3.0f*t2 + 3.0f*t + 1.0f) * (1.0f/6.0f);
                    w3 = t3 * (1.0f/6.0f);
                }
            }
            s_act[idx] = a0;                     // feature 0 = silu
#pragma unroll
            for (int j = 1; j < JF; ++j) s_act[j*HALO2 + idx] = 0.0f;
            if (cell >= 0) {
                // nonzero stored bases are (cell-3..cell) clipped to 0..10,
                // living in feature slots j = basis+1
                if (cell >= 3)               s_act[(cell-2)*HALO2 + idx] = w0;
                if (cell >= 2 && cell <= 12) s_act[(cell-1)*HALO2 + idx] = w1;
                if (cell >= 1 && cell <= 11) s_act[(cell  )*HALO2 + idx] = w2;
                if (cell <= 10)              s_act[(cell+1)*HALO2 + idx] = w3;
            }
        }

        // ---- load combined weights for channel c: [j][ky][kx][o] ----
        for (int idx = tid; idx < NW; idx += 256) {
            const int o    = idx & 15;
            const int rest = idx >> 4;        // 0..107
            const int kx   = rest % 3;
            const int ky   = (rest / 3) % 3;
            const int j    = rest / 9;        // 0..11
            float w;
            if (j == 0) w = base_w[((o*CCH + c)*3 + ky)*3 + kx];
            else        w = spline_w[((o*(CCH*KB) + (c*KB + j - 1))*3 + ky)*3 + kx];
            s_w[((j*3 + ky)*3 + kx)*CCH + o] = w;
        }
        __syncthreads();

        // ---- accumulate: 12 features x 9 taps, packed f32x2 ----
        const int rbase = rowgrp * 8;
        for (int j = 0; j < JF; ++j) {
            const float* actj = s_act + j*HALO2;
            const float* wj   = s_w + j*9*CCH + ohalf*8;
#pragma unroll
            for (int ky = 0; ky < 3; ++ky) {
#pragma unroll
                for (int kx = 0; kx < 3; ++kx) {
                    // 4 outch-pairs as one aligned LDS.64 each (broadcast per warp)
                    const unsigned long long* wp =
                        reinterpret_cast<const unsigned long long*>(wj + (ky*3 + kx)*CCH);
                    unsigned long long wv[4];
#pragma unroll
                    for (int p = 0; p < 4; ++p) wv[p] = wp[p];
#pragma unroll
                    for (int r = 0; r < 8; ++r) {
                        const float av = actj[(rbase + r + ky)*HALO + col + kx];
                        const unsigned long long a2 = pack2(av);
#pragma unroll
                        for (int p = 0; p < 4; ++p)
                            fma2(acc[r][p], a2, wv[p]);
                    }
                }
            }
        }
    }

    // ---- epilogue: unpack & write 8 pixels x 8 out channels ----
#pragma unroll
    for (int p = 0; p < 4; ++p) {
        const int o0 = ohalf*8 + 2*p;
        float* op0 = out + ((size_t)(b*CCH + o0    )) * PLANE;
        float* op1 = out + ((size_t)(b*CCH + o0 + 1)) * PLANE;
#pragma unroll
        for (int r = 0; r < 8; ++r) {
            const int gy = by + rowgrp*8 + r;
            const unsigned int lo = (unsigned int)(acc[r][p] & 0xffffffffull);
            const unsigned int hi = (unsigned int)(acc[r][p] >> 32);
            op0[gy*HW + bx + col] = __uint_as_float(lo);
            op1[gy*HW + bx + col] = __uint_as_float(hi);
        }
    }
}

// ---------------------------------------------------------------------------
// Per-(b,c) mean / rstd over one 512x512 plane. 64 blocks, deterministic.
// ---------------------------------------------------------------------------
__global__ void stats_kernel(const float* __restrict__ z,
                             float* __restrict__ mean,
                             float* __restrict__ rstd)
{
    __shared__ float sh_s[1024];
    __shared__ float sh_q[1024];
    const int bc = blockIdx.x;
    const float4* p = reinterpret_cast<const float4*>(z + (size_t)bc * PLANE);
    float s = 0.0f, q = 0.0f;
    for (int i = threadIdx.x; i < PLANE/4; i += 1024) {
        const float4 v = p[i];
        s += v.x + v.y + v.z + v.w;
        q += v.x*v.x + v.y*v.y + v.z*v.z + v.w*v.w;
    }
    sh_s[threadIdx.x] = s;
    sh_q[threadIdx.x] = q;
    __syncthreads();
    for (int off = 512; off > 0; off >>= 1) {
        if (threadIdx.x < off) {
            sh_s[threadIdx.x] += sh_s[threadIdx.x + off];
            sh_q[threadIdx.x] += sh_q[threadIdx.x + off];
        }
        __syncthreads();
    }
    if (threadIdx.x == 0) {
        const float m   = sh_s[0] * (1.0f / PLANE);
        const float var = sh_q[0] * (1.0f / PLANE) - m*m;
        mean[bc] = m;
        rstd[bc] = rsqrtf(var + 1e-5f);
    }
}

// ---------------------------------------------------------------------------
// out = sigmoid(prelu((z - mean)*rstd, alpha)), vectorized float4
// ---------------------------------------------------------------------------
__global__ void finalize_kernel(const float* __restrict__ z,
                                const float* __restrict__ mean,
                                const float* __restrict__ rstd,
                                const float* __restrict__ alpha_p,
                                float* __restrict__ out)
{
    const size_t i4 = (size_t)blockIdx.x * blockDim.x + threadIdx.x;
    if (i4 >= TOTAL/4) return;
    const int bc = (int)(i4 >> 16);   // (i4*4) / PLANE
    const float alpha = alpha_p[0];
    const float m = mean[bc], rs = rstd[bc];
    float4 v = reinterpret_cast<const float4*>(z)[i4];
    float* vp = &v.x;
#pragma unroll
    for (int k = 0; k < 4; ++k) {
        float t = (vp[k] - m) * rs;
        t = (t < 0.0f) ? alpha * t : t;
        vp[k] = 1.0f / (1.0f + __expf(-t));
    }
    reinterpret_cast<float4*>(out)[i4] = v;
}

// ---------------------------------------------------------------------------
extern "C" void kernel_launch(void* const* d_in, const int* in_sizes, int n_in,
                              void* d_out, int out_size)
{
    const float* x   = (const float*)d_in[0];
    const float* bw1 = (const float*)d_in[1];
    const float* sw1 = (const float*)d_in[2];
    const float* a1  = (const float*)d_in[3];
    const float* bw2 = (const float*)d_in[4];
    const float* sw2 = (const float*)d_in[5];
    const float* a2  = (const float*)d_in[6];
    float* out = (float*)d_out;

    float *z1, *z2, *m1, *r1, *m2, *r2;
    cudaGetSymbolAddress((void**)&z1, g_z1);
    cudaGetSymbolAddress((void**)&z2, g_z2);
    cudaGetSymbolAddress((void**)&m1, g_m1);
    cudaGetSymbolAddress((void**)&r1, g_r1);
    cudaGetSymbolAddress((void**)&m2, g_m2);
    cudaGetSymbolAddress((void**)&r2, g_r2);

    cudaFuncSetAttribute(conv_kan_kernel<false>,
                         cudaFuncAttributeMaxDynamicSharedMemorySize, SMEM_BYTES);
    cudaFuncSetAttribute(conv_kan_kernel<true>,
                         cudaFuncAttributeMaxDynamicSharedMemorySize, SMEM_BYTES);

    const dim3 grid(HW/TILE, HW/TILE, NB);   // 16 x 16 x 4

    // Layer 1
    conv_kan_kernel<false><<<grid, 256, SMEM_BYTES>>>(
        x, bw1, sw1, nullptr, nullptr, nullptr, z1);
    stats_kernel<<<NB*CCH, 1024>>>(z1, m1, r1);

    // Layer 2 (norm+prelu of layer-1 output fused into its input load)
    conv_kan_kernel<true><<<grid, 256, SMEM_BYTES>>>(
        z1, bw2, sw2, m1, r1, a1, z2);
    stats_kernel<<<NB*CCH, 1024>>>(z2, m2, r2);

    // Final norm + prelu + sigmoid
    finalize_kernel<<<(TOTAL/4 + 255)/256, 256>>>(z2, m2, r2, a2, out);
}